// round 2
// baseline (speedup 1.0000x reference)
#include <cuda_runtime.h>
#include <math.h>

// WindowAttention fused kernel, fp32 with packed f32x2 FMA (Blackwell FFMA2).
// B=4096 windows, L=49 tokens, C=128, 4 heads, head_dim=32. One CTA per window.
//
// Inputs (metadata order):
//  0: x        [4096, 49, 128] f32
//  1: W_qkv    [128, 384]      f32
//  2: b_qkv    [384]           f32
//  3: W_proj   [128, 128]      f32
//  4: b_proj   [128]           f32
//  5: rel_pos_h[13, 32]        f32
//  6: rel_pos_w[13, 32]        f32
// out: [4096, 49, 128] f32

#define NWIN 4096
#define LL   49
#define CC   128
#define QK_SCALE 0.17677669529663687f   // 32^-0.5

#define QSTRIDE  36      // q rows padded (16B aligned, conflict-free phased LDS.128)
#define WSTRIDE  132     // transposed weight tile row stride (floats)
#define AOSTRIDE 132     // attention-output staging stride

// smem layout in floats
#define OFF_X 0                          // xs [49][128]; reused as ao [49][132]
#define OFF_Q 6468                       // q  [4][49][36]
#define OFF_K 13524                      // k  [4][49][32]
#define OFF_V 19796                      // v  [4][49][32]
#define OFF_W 26068                      // wtT [128][132] (transposed weight tile)
#define OFF_R (OFF_W + 128*WSTRIDE)      // Rh [13][36], Rw [13][36]
#define SMEM_FLOATS (OFF_R + 2*13*36)
#define SMEM_BYTES  (SMEM_FLOATS * 4)

typedef unsigned long long u64;

__device__ __forceinline__ u64 fma2(u64 a, u64 b, u64 c) {
    u64 d;
    asm("fma.rn.f32x2 %0, %1, %2, %3;" : "=l"(d) : "l"(a), "l"(b), "l"(c));
    return d;
}
__device__ __forceinline__ u64 pack2(float lo, float hi) {
    u64 r;
    asm("mov.b64 %0, {%1, %2};" : "=l"(r) : "f"(lo), "f"(hi));
    return r;
}
__device__ __forceinline__ float psum(u64 v) {
    float lo, hi;
    asm("mov.b64 {%0, %1}, %2;" : "=f"(lo), "=f"(hi) : "l"(v));
    return lo + hi;
}

extern __shared__ float sm[];

__global__ void __launch_bounds__(256, 1)
win_attn_kernel(const float* __restrict__ x,
                const float* __restrict__ Wqkv,
                const float* __restrict__ bqkv,
                const float* __restrict__ Wproj,
                const float* __restrict__ bproj,
                const float* __restrict__ relh,
                const float* __restrict__ relw,
                float* __restrict__ out)
{
    const int b  = blockIdx.x;
    const int t  = threadIdx.x;
    const int tr = t >> 5;    // warp id
    const int tg = t & 31;    // lane id

    float* xs = sm + OFF_X;
    float* qs = sm + OFF_Q;
    float* ks = sm + OFF_K;
    float* vs = sm + OFF_V;
    float* wt = sm + OFF_W;
    float* Rh = sm + OFF_R;
    float* Rw = sm + OFF_R + 13 * 36;

    // ---------------- load x tile ----------------
    {
        const float4* xg = reinterpret_cast<const float4*>(x + (size_t)b * LL * CC);
        float4* xs4 = reinterpret_cast<float4*>(xs);
        #pragma unroll
        for (int i = t; i < LL * CC / 4; i += 256) xs4[i] = xg[i];
    }
    __syncthreads();

    // row assignment: rows tr, tr+8, ..., tr+48 (clamped pointers; guarded stores)
    int lrow[7];
    const ulonglong2* xr2[7];
    #pragma unroll
    for (int r = 0; r < 7; r++) {
        lrow[r] = tr + 8 * r;
        int lc = lrow[r] > 48 ? 48 : lrow[r];
        xr2[r] = reinterpret_cast<const ulonglong2*>(xs + lc * CC);
    }

    // ---------------- QKV GEMM: [49x128] @ [128x384], 3 passes ----------------
    for (int jt = 0; jt < 3; jt++) {
        // stage transposed weight tile: wtT[col][k] = Wqkv[k][jt*128+col]
        for (int i = t; i < 128 * 128; i += 256) {
            int k = i >> 7, col = i & 127;
            wt[col * WSTRIDE + k] = Wqkv[k * 384 + jt * 128 + col];
        }
        __syncthreads();

        const ulonglong2* wr2[4];
        #pragma unroll
        for (int q = 0; q < 4; q++)
            wr2[q] = reinterpret_cast<const ulonglong2*>(wt + (tg + 32 * q) * WSTRIDE);

        u64 acc[7][4];
        #pragma unroll
        for (int r = 0; r < 7; r++)
            #pragma unroll
            for (int q = 0; q < 4; q++) acc[r][q] = 0ull;

        #pragma unroll 2
        for (int c4 = 0; c4 < 32; c4++) {
            ulonglong2 wp[4];
            #pragma unroll
            for (int q = 0; q < 4; q++) wp[q] = wr2[q][c4];
            #pragma unroll
            for (int r = 0; r < 7; r++) {
                ulonglong2 xp = xr2[r][c4];     // broadcast: 4 k-values (2 pairs)
                #pragma unroll
                for (int q = 0; q < 4; q++) acc[r][q] = fma2(xp.x, wp[q].x, acc[r][q]);
                #pragma unroll
                for (int q = 0; q < 4; q++) acc[r][q] = fma2(xp.y, wp[q].y, acc[r][q]);
            }
        }

        // scatter into q/k/v per reference column map: j -> (kk=j%3, f=(j/3)%4, d=j/12)
        #pragma unroll
        for (int q = 0; q < 4; q++) {
            int j  = jt * 128 + tg + 32 * q;
            float bj = bqkv[j];
            int kk = j % 3;
            int f  = (j / 3) & 3;
            int d  = j / 12;
            float* dst;
            int stride;
            if (kk == 0)      { dst = qs + f * 49 * QSTRIDE + d; stride = QSTRIDE; }
            else if (kk == 1) { dst = ks + f * 49 * 32 + d;      stride = 32; }
            else              { dst = vs + f * 49 * 32 + d;      stride = 32; }
            #pragma unroll
            for (int r = 0; r < 7; r++) {
                if (lrow[r] < 49) dst[lrow[r] * stride] = psum(acc[r][q]) + bj;
            }
        }
        __syncthreads();
    }

    // ---------------- stage proj weights (transposed) + rel tables ----------------
    for (int i = t; i < 128 * 128; i += 256) {
        int k = i >> 7, col = i & 127;
        wt[col * WSTRIDE + k] = Wproj[k * 128 + col];
    }
    for (int i = t; i < 13 * 32; i += 256) {
        int r = i >> 5, c = i & 31;
        Rh[r * 36 + c] = relh[i];
        Rw[r * 36 + c] = relw[i];
    }
    __syncthreads();

    // ---------------- attention: one lane per (head, row) ----------------
    {
        const int f      = tr >> 1;
        const int l      = (tr & 1) * 32 + tg;
        const bool active = (l < 49);
        const int li     = active ? l : 0;

        // q row -> 16 packed pairs
        u64 q2[16];
        {
            const ulonglong2* qp = reinterpret_cast<const ulonglong2*>(qs + (f * 49 + li) * QSTRIDE);
            #pragma unroll
            for (int i = 0; i < 8; i++) {
                ulonglong2 v = qp[i];
                q2[2 * i] = v.x; q2[2 * i + 1] = v.y;
            }
        }

        // decomposed rel-pos bias terms
        const int hi = li / 7, wi = li % 7;
        float hb[7], wb[7];
        #pragma unroll
        for (int kk = 0; kk < 7; kk++) {
            const ulonglong2* rh = reinterpret_cast<const ulonglong2*>(Rh + (hi - kk + 6) * 36);
            const ulonglong2* rw = reinterpret_cast<const ulonglong2*>(Rw + (wi - kk + 6) * 36);
            u64 a0 = 0, a1 = 0, b0 = 0, b1 = 0;
            #pragma unroll
            for (int i = 0; i < 8; i++) {
                ulonglong2 hv = rh[i], wv = rw[i];
                a0 = fma2(q2[2 * i],     hv.x, a0);
                a1 = fma2(q2[2 * i + 1], hv.y, a1);
                b0 = fma2(q2[2 * i],     wv.x, b0);
                b1 = fma2(q2[2 * i + 1], wv.y, b1);
            }
            hb[kk] = psum(a0) + psum(a1);
            wb[kk] = psum(b0) + psum(b1);
        }

        // logits
        float p[49];
        const float* kh = ks + f * 49 * 32;
        {
            int j = 0;
            #pragma unroll
            for (int hj = 0; hj < 7; hj++) {
                #pragma unroll
                for (int wj = 0; wj < 7; wj++, j++) {
                    const ulonglong2* kr = reinterpret_cast<const ulonglong2*>(kh + j * 32);
                    u64 a0 = 0, a1 = 0;
                    #pragma unroll
                    for (int i = 0; i < 8; i++) {
                        ulonglong2 kv = kr[i];
                        a0 = fma2(q2[2 * i],     kv.x, a0);
                        a1 = fma2(q2[2 * i + 1], kv.y, a1);
                    }
                    p[j] = (psum(a0) + psum(a1)) * QK_SCALE + hb[hj] + wb[wj];
                }
            }
        }

        // softmax (registers)
        float mx = -1e30f;
        #pragma unroll
        for (int j = 0; j < 49; j++) mx = fmaxf(mx, p[j]);
        float s = 0.f;
        #pragma unroll
        for (int j = 0; j < 49; j++) { p[j] = __expf(p[j] - mx); s += p[j]; }
        const float inv = 1.f / s;
        #pragma unroll
        for (int j = 0; j < 49; j++) p[j] *= inv;

        // P @ V, packed over head_dim pairs
        u64 o2[16];
        #pragma unroll
        for (int i = 0; i < 16; i++) o2[i] = 0ull;
        const float* vh = vs + f * 49 * 32;
        #pragma unroll
        for (int j = 0; j < 49; j++) {
            u64 pj2 = pack2(p[j], p[j]);
            const ulonglong2* vr = reinterpret_cast<const ulonglong2*>(vh + j * 32);
            #pragma unroll
            for (int i = 0; i < 8; i++) {
                ulonglong2 vv = vr[i];
                o2[2 * i]     = fma2(pj2, vv.x, o2[2 * i]);
                o2[2 * i + 1] = fma2(pj2, vv.y, o2[2 * i + 1]);
            }
        }

        // write ao[l][f*32+d] into xs region (x no longer read by anyone)
        if (active) {
            ulonglong2* ao2 = reinterpret_cast<ulonglong2*>(xs + li * AOSTRIDE + f * 32);
            #pragma unroll
            for (int i = 0; i < 8; i++) {
                ulonglong2 v;
                v.x = o2[2 * i]; v.y = o2[2 * i + 1];
                ao2[i] = v;
            }
        }
    }
    __syncthreads();

    // ---------------- proj GEMM: [49x128] @ [128x128] + bias ----------------
    {
        const ulonglong2* ar2[7];
        #pragma unroll
        for (int r = 0; r < 7; r++) {
            int lc = lrow[r] > 48 ? 48 : lrow[r];
            ar2[r] = reinterpret_cast<const ulonglong2*>(xs + lc * AOSTRIDE);
        }
        const ulonglong2* wr2[4];
        #pragma unroll
        for (int q = 0; q < 4; q++)
            wr2[q] = reinterpret_cast<const ulonglong2*>(wt + (tg + 32 * q) * WSTRIDE);

        u64 acc[7][4];
        #pragma unroll
        for (int r = 0; r < 7; r++)
            #pragma unroll
            for (int q = 0; q < 4; q++) acc[r][q] = 0ull;

        #pragma unroll 2
        for (int c4 = 0; c4 < 32; c4++) {
            ulonglong2 wp[4];
            #pragma unroll
            for (int q = 0; q < 4; q++) wp[q] = wr2[q][c4];
            #pragma unroll
            for (int r = 0; r < 7; r++) {
                ulonglong2 xp = ar2[r][c4];
                #pragma unroll
                for (int q = 0; q < 4; q++) acc[r][q] = fma2(xp.x, wp[q].x, acc[r][q]);
                #pragma unroll
                for (int q = 0; q < 4; q++) acc[r][q] = fma2(xp.y, wp[q].y, acc[r][q]);
            }
        }

        float bj[4];
        #pragma unroll
        for (int q = 0; q < 4; q++) bj[q] = bproj[tg + 32 * q];

        #pragma unroll
        for (int r = 0; r < 7; r++) {
            if (lrow[r] < 49) {
                float* orow = out + ((size_t)b * 49 + lrow[r]) * 128;
                #pragma unroll
                for (int q = 0; q < 4; q++)
                    orow[tg + 32 * q] = psum(acc[r][q]) + bj[q];
            }
        }
    }
}

extern "C" void kernel_launch(void* const* d_in, const int* in_sizes, int n_in,
                              void* d_out, int out_size)
{
    const float* x     = (const float*)d_in[0];
    const float* Wqkv  = (const float*)d_in[1];
    const float* bqkv  = (const float*)d_in[2];
    const float* Wproj = (const float*)d_in[3];
    const float* bproj = (const float*)d_in[4];
    const float* relh  = (const float*)d_in[5];
    const float* relw  = (const float*)d_in[6];
    float* out = (float*)d_out;

    cudaFuncSetAttribute(win_attn_kernel,
                         cudaFuncAttributeMaxDynamicSharedMemorySize, SMEM_BYTES);

    win_attn_kernel<<<NWIN, 256, SMEM_BYTES>>>(x, Wqkv, bqkv, Wproj, bproj,
                                               relh, relw, out);
}